// round 2
// baseline (speedup 1.0000x reference)
#include <cuda_runtime.h>
#include <cuda_bf16.h>
#include <cstdint>

#define NB2 128   // persistent blocks in recurrent kernel (must be <= 148)

// ------------------------------------------------------------------
// Device-global scratch (allocation-free)
// ------------------------------------------------------------------
__device__ float d_Gx[(size_t)16384 * 4096];     // x@Wx + bias, row=b*512+t, col=gate*1024+j
__device__ float d_H2[(size_t)16384 * 1024];     // h in [b*512+t][j] layout (for final FC)
__device__ float d_Hts[(size_t)513 * 1024 * 32]; // h in [t][k][b] layout (for recurrence)
__device__ float d_Wx[(size_t)512 * 4096];       // packed input-projection weights
__device__ float d_bx[4096];                     // packed gate biases
__device__ unsigned d_cnt[512];                  // per-step grid-barrier counters

// ------------------------------------------------------------------
// Helpers
// ------------------------------------------------------------------
__device__ __forceinline__ unsigned cvt_tf32(float x) {
    unsigned u;
    asm("cvt.rna.tf32.f32 %0, %1;" : "=r"(u) : "f"(x));
    return u;
}

__device__ __forceinline__ void mma_tf32(float c[4],
                                         unsigned a0, unsigned a1, unsigned a2, unsigned a3,
                                         unsigned b0, unsigned b1) {
    asm volatile(
        "mma.sync.aligned.m16n8k8.row.col.f32.tf32.tf32.f32 "
        "{%0,%1,%2,%3},{%4,%5,%6,%7},{%8,%9},{%0,%1,%2,%3};"
        : "+f"(c[0]), "+f"(c[1]), "+f"(c[2]), "+f"(c[3])
        : "r"(a0), "r"(a1), "r"(a2), "r"(a3), "r"(b0), "r"(b1));
}

__device__ __forceinline__ float sigm(float x) { return 1.f / (1.f + __expf(-x)); }

// ------------------------------------------------------------------
// Init: zero h_0 slab and barrier counters (runs every launch/replay)
// ------------------------------------------------------------------
__global__ void init_kernel() {
    int idx = blockIdx.x * blockDim.x + threadIdx.x;
    if (idx < 32768) d_Hts[idx] = 0.f;
    if (idx < 512) d_cnt[idx] = 0u;
}

// ------------------------------------------------------------------
// Pack Wx = [Wf|Wi|Wg|Wo] rows [0,512), and the gate biases
// ------------------------------------------------------------------
__global__ void pack_kernel(const float* __restrict__ Wf, const float* __restrict__ Wi,
                            const float* __restrict__ Wg, const float* __restrict__ Wo,
                            const float* __restrict__ bf, const float* __restrict__ bi,
                            const float* __restrict__ bg, const float* __restrict__ bo) {
    int idx = blockIdx.x * blockDim.x + threadIdx.x;
    if (idx < 512 * 1024) {
        int k = idx >> 10, j = idx & 1023;
        size_t o = (size_t)k * 4096 + j;
        d_Wx[o]        = Wf[idx];
        d_Wx[o + 1024] = Wi[idx];
        d_Wx[o + 2048] = Wg[idx];
        d_Wx[o + 3072] = Wo[idx];
    }
    if (idx < 1024) {
        d_bx[idx]        = bf[idx];
        d_bx[idx + 1024] = bi[idx];
        d_bx[idx + 2048] = bg[idx];
        d_bx[idx + 3072] = bo[idx];
    }
}

// ------------------------------------------------------------------
// tf32 GEMM: C[M,N] = A[M,K] @ B[K,N] + bias[N]
// 128x128x16 tiles, 8 warps (warp tile 64x32), single-buffered smem.
// Requires M%128==0, N%128==0, K%16==0 (true for all our shapes).
// ------------------------------------------------------------------
__global__ void __launch_bounds__(256) gemm_tf32_bias(
    const float* __restrict__ A, const float* __restrict__ Bm,
    const float* __restrict__ bias, float* __restrict__ C,
    int M, int N, int K) {
    __shared__ float sA[128 * 20];  // 128 rows x 16 (+4 pad)
    __shared__ float sB[16 * 132];  // 16 rows x 128 (+4 pad)

    const int tid = threadIdx.x;
    const int w = tid >> 5, lane = tid & 31;
    const int g = lane >> 2, tig = lane & 3;
    const int wm = (w >> 2) * 64, wn = (w & 3) * 32;
    const int m0 = blockIdx.y * 128, n0 = blockIdx.x * 128;

    float Cr[4][4][4];
#pragma unroll
    for (int a = 0; a < 4; a++)
#pragma unroll
        for (int b = 0; b < 4; b++)
#pragma unroll
            for (int c = 0; c < 4; c++) Cr[a][b][c] = 0.f;

    const int nk = K / 16;
    for (int kc = 0; kc < nk; kc++) {
        const int k0 = kc * 16;
        __syncthreads();  // prior compute done before smem overwrite
        // Load A slab: 128x16 floats (512 float4, 2 per thread)
#pragma unroll
        for (int i = 0; i < 2; i++) {
            int lin = tid + i * 256;
            int r = lin >> 2, q = lin & 3;
            float4 v = *(const float4*)(A + (size_t)(m0 + r) * K + k0 + q * 4);
            *(float4*)(sA + r * 20 + q * 4) = v;
        }
        // Load B slab: 16x128 floats (512 float4, 2 per thread)
#pragma unroll
        for (int i = 0; i < 2; i++) {
            int lin = tid + i * 256;
            int r = lin >> 5, q = lin & 31;
            float4 v = *(const float4*)(Bm + (size_t)(k0 + r) * N + n0 + q * 4);
            *(float4*)(sB + r * 132 + q * 4) = v;
        }
        __syncthreads();

#pragma unroll
        for (int k8 = 0; k8 < 2; k8++) {
            unsigned bf_[4][2];
#pragma unroll
            for (int nt = 0; nt < 4; nt++) {
                bf_[nt][0] = cvt_tf32(sB[(k8 * 8 + tig) * 132 + wn + nt * 8 + g]);
                bf_[nt][1] = cvt_tf32(sB[(k8 * 8 + tig + 4) * 132 + wn + nt * 8 + g]);
            }
#pragma unroll
            for (int mt = 0; mt < 4; mt++) {
                const float* ap = sA + (wm + mt * 16 + g) * 20 + k8 * 8 + tig;
                unsigned a0 = cvt_tf32(ap[0]);
                unsigned a1 = cvt_tf32(ap[8 * 20]);
                unsigned a2 = cvt_tf32(ap[4]);
                unsigned a3 = cvt_tf32(ap[8 * 20 + 4]);
#pragma unroll
                for (int nt = 0; nt < 4; nt++)
                    mma_tf32(Cr[mt][nt], a0, a1, a2, a3, bf_[nt][0], bf_[nt][1]);
            }
        }
    }

    // Epilogue: add bias, store (float2 per fragment row)
#pragma unroll
    for (int mt = 0; mt < 4; mt++) {
#pragma unroll
        for (int nt = 0; nt < 4; nt++) {
            int row = m0 + wm + mt * 16 + g;
            int col = n0 + wn + nt * 8 + 2 * tig;
            float bx = bias[col], by = bias[col + 1];
            float2 v0 = make_float2(Cr[mt][nt][0] + bx, Cr[mt][nt][1] + by);
            float2 v1 = make_float2(Cr[mt][nt][2] + bx, Cr[mt][nt][3] + by);
            *(float2*)(C + (size_t)row * N + col) = v0;
            *(float2*)(C + (size_t)(row + 8) * N + col) = v1;
        }
    }
}

// ------------------------------------------------------------------
// Persistent recurrent kernel. 128 blocks x 256 threads.
// Block bk owns hidden units [bk*8, bk*8+8) x 4 gates (32 gate columns).
// Wh slice lives in registers as tf32 B-fragments (loaded once).
// ------------------------------------------------------------------
__global__ void __launch_bounds__(256) lstm_rec(
    const float* __restrict__ Wf, const float* __restrict__ Wi,
    const float* __restrict__ Wg, const float* __restrict__ Wo) {
    __shared__ float sPart[8 * 1056];  // 8 warps x 32x32 partials (row stride 33)

    const int tid = threadIdx.x;
    const int w = tid >> 5, lane = tid & 31;
    const int g = lane >> 2, tig = lane & 3;
    const int kw = w * 128;            // this warp's K-slice base
    const int bk = blockIdx.x;

    // ---- Preload weights into registers as tf32 fragments ----
    // Fragment (ks, nt): B tile rows k = kw+ks*8+tig (+4), col = bk*8 + g, gate = nt
    const float* Wp[4] = {Wf, Wi, Wg, Wo};
    unsigned Wr[16][4][2];
#pragma unroll
    for (int ks = 0; ks < 16; ks++) {
#pragma unroll
        for (int nt = 0; nt < 4; nt++) {
            const float* ws = Wp[nt] + (size_t)(512 + kw + ks * 8 + tig) * 1024 + bk * 8 + g;
            Wr[ks][nt][0] = cvt_tf32(__ldg(ws));
            Wr[ks][nt][1] = cvt_tf32(__ldg(ws + 4 * 1024));
        }
    }

    // State-update thread mapping: b = tid/8, uu = tid%8
    const int b_ = tid >> 3, uu = tid & 7;
    float creg = 0.f;

    const float* gxbase = d_Gx + (size_t)(b_ * 512) * 4096 + bk * 8 + uu;

    for (int t = 0; t < 512; t++) {
        // Prefetch this step's input-projection gate values (independent of h)
        const float* gxp = gxbase + (size_t)t * 4096;
        float gx0 = __ldg(gxp);
        float gx1 = __ldg(gxp + 1024);
        float gx2 = __ldg(gxp + 2048);
        float gx3 = __ldg(gxp + 3072);

        // ---- h_t @ Wh_slice : each warp reduces its K=128 slice ----
        float Cr[2][4][4];
#pragma unroll
        for (int mt = 0; mt < 2; mt++)
#pragma unroll
            for (int nt = 0; nt < 4; nt++)
#pragma unroll
                for (int c = 0; c < 4; c++) Cr[mt][nt][c] = 0.f;

        const float* htp = d_Hts + (size_t)t * 32768 + kw * 32;
#pragma unroll
        for (int ks = 0; ks < 16; ks++) {
            const float* hb = htp + (ks * 8 + tig) * 32;
#pragma unroll
            for (int mt = 0; mt < 2; mt++) {
                unsigned a0 = cvt_tf32(__ldcg(hb + mt * 16 + g));
                unsigned a1 = cvt_tf32(__ldcg(hb + mt * 16 + g + 8));
                unsigned a2 = cvt_tf32(__ldcg(hb + 4 * 32 + mt * 16 + g));
                unsigned a3 = cvt_tf32(__ldcg(hb + 4 * 32 + mt * 16 + g + 8));
#pragma unroll
                for (int nt = 0; nt < 4; nt++)
                    mma_tf32(Cr[mt][nt], a0, a1, a2, a3, Wr[ks][nt][0], Wr[ks][nt][1]);
            }
        }

        // ---- Store per-warp partials to smem ----
        {
            float* sp = sPart + w * 1056;
#pragma unroll
            for (int mt = 0; mt < 2; mt++) {
#pragma unroll
                for (int nt = 0; nt < 4; nt++) {
                    int row = mt * 16 + g, col = nt * 8 + 2 * tig;
                    sp[row * 33 + col]       = Cr[mt][nt][0];
                    sp[row * 33 + col + 1]   = Cr[mt][nt][1];
                    sp[(row + 8) * 33 + col]     = Cr[mt][nt][2];
                    sp[(row + 8) * 33 + col + 1] = Cr[mt][nt][3];
                }
            }
        }
        __syncthreads();

        // ---- Cross-warp reduce + gate nonlinearity + state update ----
        float red[4];
#pragma unroll
        for (int gate = 0; gate < 4; gate++) {
            float s = 0.f;
#pragma unroll
            for (int w2 = 0; w2 < 8; w2++)
                s += sPart[w2 * 1056 + b_ * 33 + gate * 8 + uu];
            red[gate] = s;
        }
        float F = red[0] + gx0;
        float I = red[1] + gx1;
        float G = red[2] + gx2;
        float O = red[3] + gx3;
        creg = sigm(F) * creg + sigm(I) * tanhf(G);
        float h = sigm(O) * tanhf(creg);

        // Write h in both layouts
        d_Hts[(size_t)(t + 1) * 32768 + (bk * 8 + uu) * 32 + b_] = h;
        d_H2[(size_t)(b_ * 512 + t) * 1024 + bk * 8 + uu] = h;

        // ---- Grid barrier ----
        __syncthreads();   // also protects sPart reuse next step
        __threadfence();
        if (tid == 0) {
            unsigned arrived = atomicAdd(&d_cnt[t], 1u) + 1u;
            if (arrived < NB2) {
                volatile unsigned* vc = d_cnt;
                while (vc[t] < NB2) {}
            }
        }
        __syncthreads();
    }
}

// ------------------------------------------------------------------
// Launch sequence (graph-capturable: kernel launches only)
// ------------------------------------------------------------------
extern "C" void kernel_launch(void* const* d_in, const int* in_sizes, int n_in,
                              void* d_out, int out_size) {
    const float* x    = (const float*)d_in[0];
    const float* W_f  = (const float*)d_in[1];
    const float* b_f  = (const float*)d_in[2];
    const float* W_i  = (const float*)d_in[3];
    const float* b_i  = (const float*)d_in[4];
    const float* W_g  = (const float*)d_in[5];
    const float* b_g  = (const float*)d_in[6];
    const float* W_o  = (const float*)d_in[7];
    const float* b_o  = (const float*)d_in[8];
    const float* W_fc = (const float*)d_in[9];
    const float* b_fc = (const float*)d_in[10];
    float* out = (float*)d_out;

    void *pGx, *pH2, *pWx, *pbx;
    cudaGetSymbolAddress(&pGx, d_Gx);
    cudaGetSymbolAddress(&pH2, d_H2);
    cudaGetSymbolAddress(&pWx, d_Wx);
    cudaGetSymbolAddress(&pbx, d_bx);

    init_kernel<<<128, 256>>>();
    pack_kernel<<<2048, 256>>>(W_f, W_i, W_g, W_o, b_f, b_i, b_g, b_o);

    // Phase 1: Gx = x @ Wx + bx   (M=16384, N=4096, K=512)
    gemm_tf32_bias<<<dim3(32, 128), 256>>>(
        x, (const float*)pWx, (const float*)pbx, (float*)pGx, 16384, 4096, 512);

    // Phase 2: recurrence (persistent)
    lstm_rec<<<NB2, 256>>>(W_f, W_i, W_g, W_o);

    // Phase 3: out = H2 @ W_fc + b_fc   (M=16384, N=512, K=1024)
    gemm_tf32_bias<<<dim3(4, 128), 256>>>(
        (const float*)pH2, W_fc, b_fc, out, 16384, 512, 1024);
}